// round 5
// baseline (speedup 1.0000x reference)
#include <cuda_runtime.h>

#define N_FEATS 9
#define VOCAB   119
#define HIDDEN  128
#define MAXN    50176     // capacity for scratch (N = 50000 in this problem)
#define TILE_M  128       // nodes per CTA in encode
#define HSTR    132       // padded smem stride (conflict-free fragment loads)

// Scratch for q/k/v between the two kernels (no allocations allowed).
__device__ float g_q[MAXN * HIDDEN];
__device__ float g_k[MAXN * HIDDEN];
__device__ float g_v[MAXN * HIDDEN];

// 1 if nbr_mask buffer is int32-encoded bools, 0 if uint8-encoded.
__device__ int g_mask_i32;

// ---------------------------------------------------------------------------
// tf32 helpers
// ---------------------------------------------------------------------------
__device__ __forceinline__ float to_tf32(float x) {
    float r;
    asm("cvt.rna.tf32.f32 %0, %1;" : "=f"(r) : "f"(x));
    return r;
}

__device__ __forceinline__ void mma_tf32(float d[4], const unsigned a[4],
                                         unsigned b0, unsigned b1) {
    asm volatile(
        "mma.sync.aligned.m16n8k8.row.col.f32.tf32.tf32.f32 "
        "{%0,%1,%2,%3}, {%4,%5,%6,%7}, {%8,%9}, {%0,%1,%2,%3};"
        : "+f"(d[0]), "+f"(d[1]), "+f"(d[2]), "+f"(d[3])
        : "r"(a[0]), "r"(a[1]), "r"(a[2]), "r"(a[3]), "r"(b0), "r"(b1));
}

// ---------------------------------------------------------------------------
// Kernel 1: AtomEncoder + fused Q/K/V projections on tensor cores (tf32).
// CTA = 128 nodes, 256 threads (8 warps, warp w owns rows w*16..w*16+15).
// h tile and one W matrix staged in dynamic smem with stride-132 padding.
// A fragments (h) live in 64 regs/thread, reused for all 3 GEMMs; W staged
// sequentially (q, k, v) into the same smem buffer.
// Block 0 additionally detects the nbr_mask dtype (i32 vs u8 bools).
// ---------------------------------------------------------------------------
__global__ __launch_bounds__(256) void k_encode_qkv(
    const int*   __restrict__ X,       // [N][9]
    const float* __restrict__ emb,     // [9][119][128]
    const float* __restrict__ Wq, const float* __restrict__ bq,
    const float* __restrict__ Wk, const float* __restrict__ bk,
    const float* __restrict__ Wv, const float* __restrict__ bv,
    const unsigned char* __restrict__ nbr_mask,
    int N)
{
    extern __shared__ float smem[];
    float* sh_h = smem;                         // [128][HSTR] tf32 h tile
    float* sw   = smem + TILE_M * HSTR;         // [128][HSTR] tf32 W tile
    int*   sh_x = (int*)(sw + HIDDEN * HSTR);   // [128][9]

    const int tid   = threadIdx.x;
    const int node0 = blockIdx.x * TILE_M;

    // --- mask dtype detection (block 0 only; int32 bools -> bytes 1..3 zero)
    if (blockIdx.x == 0) {
        int ok = 1;
        for (int g = tid; g < 1024; g += 256)
            if (nbr_mask[g * 4 + 1] | nbr_mask[g * 4 + 2] | nbr_mask[g * 4 + 3])
                ok = 0;
        ok = __syncthreads_and(ok);
        if (tid == 0) g_mask_i32 = ok;
    }

    // --- stage X (clamped for tail; output stores are guarded later)
    for (int i = tid; i < TILE_M * N_FEATS; i += 256) {
        const int node = min(node0 + i / N_FEATS, N - 1);
        sh_x[i] = X[node * N_FEATS + (i % N_FEATS)];
    }
    __syncthreads();

    // --- embedding sum -> h (f32 accumulate, round once to tf32)
    for (int i = tid; i < TILE_M * HIDDEN; i += 256) {
        const int node = i >> 7;
        const int c    = i & 127;
        float s = 0.f;
#pragma unroll
        for (int f = 0; f < N_FEATS; f++) {
            const int x = sh_x[node * N_FEATS + f];
            s += emb[(f * VOCAB + x) * HIDDEN + c];
        }
        sh_h[node * HSTR + c] = to_tf32(s);
    }
    __syncthreads();

    // --- load A fragments (h) once: 16 k-chunks x 4 regs
    const int warp = tid >> 5;
    const int lane = tid & 31;
    const int m0   = warp * 16;
    const int ar   = m0 + (lane >> 2);    // fragment row (and +8)
    const int ac   = lane & 3;            // fragment col (and +4)

    unsigned afrag[64];
#pragma unroll
    for (int kc = 0; kc < 16; kc++) {
        const int k0 = kc * 8;
        afrag[kc * 4 + 0] = __float_as_uint(sh_h[ar * HSTR + k0 + ac]);
        afrag[kc * 4 + 1] = __float_as_uint(sh_h[(ar + 8) * HSTR + k0 + ac]);
        afrag[kc * 4 + 2] = __float_as_uint(sh_h[ar * HSTR + k0 + ac + 4]);
        afrag[kc * 4 + 3] = __float_as_uint(sh_h[(ar + 8) * HSTR + k0 + ac + 4]);
    }

    const float* Ws[3] = {Wq, Wk, Wv};
    const float* Bs[3] = {bq, bk, bv};
    float*       Os[3] = {g_q, g_k, g_v};
    const float  Ss[3] = {0.25f, 1.0f, 1.0f};   // q scaling = 16^-0.5

    const int brow = lane & 3;      // B fragment k offset
    const int bcol = lane >> 2;     // B fragment n offset
    const int orow0 = node0 + m0 + (lane >> 2);
    const int ocol  = (lane & 3) * 2;

    for (int g = 0; g < 3; g++) {
        // stage W (rounded to tf32)
        const float* W = Ws[g];
        __syncthreads();   // previous gemm done reading sw
        for (int i = tid; i < HIDDEN * HIDDEN; i += 256) {
            const int j = i >> 7;
            const int c = i & 127;
            sw[j * HSTR + c] = to_tf32(W[i]);
        }
        __syncthreads();

        const float* bias  = Bs[g];
        float*       out   = Os[g];
        const float  scale = Ss[g];

        // n-chunks in pairs -> 2 independent accumulator chains
#pragma unroll
        for (int np = 0; np < 8; np++) {
            const int c0 = np * 16;
            float acc0[4] = {0.f, 0.f, 0.f, 0.f};
            float acc1[4] = {0.f, 0.f, 0.f, 0.f};
#pragma unroll
            for (int kc = 0; kc < 16; kc++) {
                const int k0 = kc * 8;
                const float* wb = &sw[(k0 + brow) * HSTR + bcol];
                const unsigned b00 = __float_as_uint(wb[c0]);
                const unsigned b01 = __float_as_uint(wb[4 * HSTR + c0]);
                const unsigned b10 = __float_as_uint(wb[c0 + 8]);
                const unsigned b11 = __float_as_uint(wb[4 * HSTR + c0 + 8]);
                mma_tf32(acc0, &afrag[kc * 4], b00, b01);
                mma_tf32(acc1, &afrag[kc * 4], b10, b11);
            }
            // epilogue: bias + scale, guarded stores
            const int c00 = c0 + ocol;
            const float bx0 = bias[c00],     by0 = bias[c00 + 1];
            const float bx1 = bias[c00 + 8], by1 = bias[c00 + 9];
            if (orow0 < N) {
                float2* p = reinterpret_cast<float2*>(&out[orow0 * HIDDEN + c00]);
                p[0] = make_float2((acc0[0] + bx0) * scale, (acc0[1] + by0) * scale);
                p[4] = make_float2((acc1[0] + bx1) * scale, (acc1[1] + by1) * scale);
            }
            if (orow0 + 8 < N) {
                float2* p = reinterpret_cast<float2*>(&out[(orow0 + 8) * HIDDEN + c00]);
                p[0] = make_float2((acc0[2] + bx0) * scale, (acc0[3] + by0) * scale);
                p[4] = make_float2((acc1[2] + bx1) * scale, (acc1[3] + by1) * scale);
            }
        }
    }
}

// ---------------------------------------------------------------------------
// Kernel 2: ELL sparse attention. One warp per node. Lane l owns dims
// [4l, 4l+4) -> head = l>>2; head-dot reduced with 2x shfl_xor inside the
// 4-lane group. V rows held in 64 registers to avoid a second gather pass.
// ---------------------------------------------------------------------------
__global__ __launch_bounds__(256, 2) void k_attn(
    const int*           __restrict__ nbr_idx,   // [N][16]
    const unsigned char* __restrict__ nbr_mask,  // [N][16] bools (u8 or i32)
    float*               __restrict__ out,       // [N][128]
    int N)
{
    const int warp = (blockIdx.x * blockDim.x + threadIdx.x) >> 5;
    const int lane = threadIdx.x & 31;
    if (warp >= N) return;
    const int n = warp;

    const int mask_i32 = g_mask_i32;

    int      jreg = 0;
    unsigned mreg = 0;
    if (lane < 16) {
        jreg = nbr_idx[n * 16 + lane];
        mreg = mask_i32
             ? (unsigned)reinterpret_cast<const int*>(nbr_mask)[n * 16 + lane]
             : (unsigned)nbr_mask[n * 16 + lane];
    }

    const float4 q4 = reinterpret_cast<const float4*>(g_q)[n * 32 + lane];

    float  sc[16];
    float4 vb[16];
#pragma unroll
    for (int kk = 0; kk < 16; kk++) {
        const int      j = __shfl_sync(0xffffffffu, jreg, kk);
        const unsigned m = __shfl_sync(0xffffffffu, mreg, kk);
        const float4  kv = reinterpret_cast<const float4*>(g_k)[j * 32 + lane];
        vb[kk]           = reinterpret_cast<const float4*>(g_v)[j * 32 + lane];
        float d = q4.x * kv.x + q4.y * kv.y + q4.z * kv.z + q4.w * kv.w;
        d += __shfl_xor_sync(0xffffffffu, d, 1);
        d += __shfl_xor_sync(0xffffffffu, d, 2);   // full 16-dim head dot
        sc[kk] = m ? d : -1e9f;
    }

    // Softmax over the 16 neighbors (per head; replicated across the 4 lanes).
    float mx = -1e30f;
#pragma unroll
    for (int kk = 0; kk < 16; kk++) mx = fmaxf(mx, sc[kk]);
    float s = 0.f;
#pragma unroll
    for (int kk = 0; kk < 16; kk++) { sc[kk] = __expf(sc[kk] - mx); s += sc[kk]; }
    const float inv = 1.f / s;

    float4 acc = make_float4(0.f, 0.f, 0.f, 0.f);
#pragma unroll
    for (int kk = 0; kk < 16; kk++) {
        const float p = sc[kk] * inv;
        acc.x = fmaf(p, vb[kk].x, acc.x);
        acc.y = fmaf(p, vb[kk].y, acc.y);
        acc.z = fmaf(p, vb[kk].z, acc.z);
        acc.w = fmaf(p, vb[kk].w, acc.w);
    }
    reinterpret_cast<float4*>(out)[n * 32 + lane] = acc;
}

// ---------------------------------------------------------------------------
// Launch
// ---------------------------------------------------------------------------
extern "C" void kernel_launch(void* const* d_in, const int* in_sizes, int n_in,
                              void* d_out, int out_size)
{
    const int*           X        = (const int*)d_in[0];
    const int*           nbr_idx  = (const int*)d_in[1];
    const unsigned char* nbr_mask = (const unsigned char*)d_in[2];
    const float*         emb      = (const float*)d_in[3];
    const float*         Wq       = (const float*)d_in[4];
    const float*         bq       = (const float*)d_in[5];
    const float*         Wk       = (const float*)d_in[6];
    const float*         bk       = (const float*)d_in[7];
    const float*         Wv       = (const float*)d_in[8];
    const float*         bv       = (const float*)d_in[9];
    float*               out      = (float*)d_out;

    const int N = in_sizes[0] / N_FEATS;

    const int smem_bytes = (TILE_M * HSTR + HIDDEN * HSTR) * 4
                         + TILE_M * N_FEATS * 4;   // ~139.8 KB
    cudaFuncSetAttribute(k_encode_qkv,
                         cudaFuncAttributeMaxDynamicSharedMemorySize, smem_bytes);

    const int grid1 = (N + TILE_M - 1) / TILE_M;
    k_encode_qkv<<<grid1, 256, smem_bytes>>>(X, emb, Wq, bq, Wk, bk, Wv, bv,
                                             nbr_mask, N);

    const int grid2 = (N + 7) / 8;   // 8 warps per 256-thread block
    k_attn<<<grid2, 256>>>(nbr_idx, nbr_mask, out, N);
}

// round 7
// speedup vs baseline: 2.4062x; 2.4062x over previous
#include <cuda_runtime.h>
#include <cstdint>

#define N_FEATS 9
#define VOCAB   119
#define HIDDEN  128
#define MAXN    50176
#define TILE_M  128
#define HSTR    132      // padded smem stride for h tile

// Scratch (no allocations allowed).
__device__ float g_q[MAXN * HIDDEN];
__device__ float g_k[MAXN * HIDDEN];
__device__ float g_v[MAXN * HIDDEN];
// W pre-packed into mma B-fragment order: [3][8 np][16 kc][32 lane] uint4
__device__ uint4 g_wb[3 * 8 * 16 * 32];
__device__ int   g_mask_i32;

__device__ __forceinline__ uint32_t to_tf32(float x) {
    uint32_t r;
    asm("cvt.rna.tf32.f32 %0, %1;" : "=r"(r) : "f"(x));
    return r;
}

__device__ __forceinline__ void mma_tf32(float d[4], const uint32_t a[4],
                                         uint32_t b0, uint32_t b1) {
    asm volatile(
        "mma.sync.aligned.m16n8k8.row.col.f32.tf32.tf32.f32 "
        "{%0,%1,%2,%3}, {%4,%5,%6,%7}, {%8,%9}, {%0,%1,%2,%3};"
        : "+f"(d[0]), "+f"(d[1]), "+f"(d[2]), "+f"(d[3])
        : "r"(a[0]), "r"(a[1]), "r"(a[2]), "r"(a[3]), "r"(b0), "r"(b1));
}

// ---------------------------------------------------------------------------
// Prep: pack W (tf32-rounded) into fragment order + detect mask dtype.
// Fragment mapping identical to the validated R5 smem indexing:
//   brow = lane&3, bcol = lane>>2, c0 = np*16, k0 = kc*8
//   b00 = W[(k0+brow)  *128 + c0+bcol  ]   b01 = W[(k0+brow+4)*128 + c0+bcol  ]
//   b10 = W[(k0+brow)  *128 + c0+bcol+8]   b11 = W[(k0+brow+4)*128 + c0+bcol+8]
// ---------------------------------------------------------------------------
__global__ __launch_bounds__(512) void k_prep(
    const float* __restrict__ Wq, const float* __restrict__ Wk,
    const float* __restrict__ Wv, const unsigned char* __restrict__ mask)
{
    const int bid = blockIdx.x;
    if (bid < 24) {
        const int i    = bid * 512 + threadIdx.x;   // 0..12287
        const int lane = i & 31;
        const int kc   = (i >> 5) & 15;
        const int np   = (i >> 9) & 7;
        const int g    = i >> 12;
        const float* W = (g == 0) ? Wq : (g == 1) ? Wk : Wv;
        const int brow = lane & 3, bcol = lane >> 2;
        const int k0 = kc * 8, c0 = np * 16;
        uint4 u;
        u.x = to_tf32(W[(k0 + brow)     * 128 + c0 + bcol]);
        u.y = to_tf32(W[(k0 + brow + 4) * 128 + c0 + bcol]);
        u.z = to_tf32(W[(k0 + brow)     * 128 + c0 + bcol + 8]);
        u.w = to_tf32(W[(k0 + brow + 4) * 128 + c0 + bcol + 8]);
        g_wb[i] = u;
    } else {
        int ok = 1;
        for (int gi = threadIdx.x; gi < 1024; gi += 512)
            if (mask[gi * 4 + 1] | mask[gi * 4 + 2] | mask[gi * 4 + 3]) ok = 0;
        ok = __syncthreads_and(ok);
        if (threadIdx.x == 0) g_mask_i32 = ok;
    }
}

// ---------------------------------------------------------------------------
// Encode: AtomEncoder + 3x tf32 mma.sync GEMM. 128 nodes/CTA, 256 threads.
// Only the h tile lives in smem (72KB -> 2 CTAs/SM); W fragments stream from
// g_wb via coalesced LDG.128 (L1/L2 resident). Two __syncthreads total.
// ---------------------------------------------------------------------------
__global__ __launch_bounds__(256) void k_encode_qkv(
    const int*   __restrict__ X,
    const float* __restrict__ emb,
    const float* __restrict__ bq, const float* __restrict__ bk,
    const float* __restrict__ bv, int N)
{
    extern __shared__ float smem[];
    float* sh_h = smem;                            // [128][HSTR] tf32-rounded h
    int*   sh_x = (int*)(smem + TILE_M * HSTR);    // [128][9]

    const int tid   = threadIdx.x;
    const int node0 = blockIdx.x * TILE_M;

    for (int i = tid; i < TILE_M * N_FEATS; i += 256) {
        const int node = min(node0 + i / N_FEATS, N - 1);
        sh_x[i] = X[node * N_FEATS + (i % N_FEATS)];
    }
    __syncthreads();

    // h = sum of 9 embedding rows (float4 per thread-iter), tf32-rounded.
    for (int gi = tid; gi < TILE_M * 32; gi += 256) {
        const int node = gi >> 5;
        const int c0   = (gi & 31) * 4;
        float4 s = make_float4(0.f, 0.f, 0.f, 0.f);
#pragma unroll
        for (int f = 0; f < N_FEATS; f++) {
            const int x = sh_x[node * N_FEATS + f];
            const float4 e = *reinterpret_cast<const float4*>(
                &emb[(f * VOCAB + x) * HIDDEN + c0]);
            s.x += e.x; s.y += e.y; s.z += e.z; s.w += e.w;
        }
        float* hp = &sh_h[node * HSTR + c0];
        hp[0] = __uint_as_float(to_tf32(s.x));
        hp[1] = __uint_as_float(to_tf32(s.y));
        hp[2] = __uint_as_float(to_tf32(s.z));
        hp[3] = __uint_as_float(to_tf32(s.w));
    }
    __syncthreads();

    // A fragments (h) once: 16 k-chunks x 4 regs.
    const int warp = tid >> 5;
    const int lane = tid & 31;
    const int m0   = warp * 16;
    const int ar   = m0 + (lane >> 2);
    const int ac   = lane & 3;

    uint32_t afrag[64];
#pragma unroll
    for (int kc = 0; kc < 16; kc++) {
        const int k0 = kc * 8;
        afrag[kc * 4 + 0] = __float_as_uint(sh_h[ar * HSTR + k0 + ac]);
        afrag[kc * 4 + 1] = __float_as_uint(sh_h[(ar + 8) * HSTR + k0 + ac]);
        afrag[kc * 4 + 2] = __float_as_uint(sh_h[ar * HSTR + k0 + ac + 4]);
        afrag[kc * 4 + 3] = __float_as_uint(sh_h[(ar + 8) * HSTR + k0 + ac + 4]);
    }

    const float* Bs[3] = {bq, bk, bv};
    float*       Os[3] = {g_q, g_k, g_v};
    const float  Ss[3] = {0.25f, 1.0f, 1.0f};

    const int orow0 = node0 + m0 + (lane >> 2);
    const int ocol  = (lane & 3) * 2;

    for (int g = 0; g < 3; g++) {
        const float* bias  = Bs[g];
        float*       out   = Os[g];
        const float  scale = Ss[g];

#pragma unroll
        for (int np = 0; np < 8; np++) {
            float acc0[4] = {0.f, 0.f, 0.f, 0.f};
            float acc1[4] = {0.f, 0.f, 0.f, 0.f};
            const uint4* wp = &g_wb[((g * 8 + np) * 16) * 32 + lane];
#pragma unroll
            for (int kc = 0; kc < 16; kc++) {
                const uint4 b = wp[kc * 32];
                mma_tf32(acc0, &afrag[kc * 4], b.x, b.y);
                mma_tf32(acc1, &afrag[kc * 4], b.z, b.w);
            }
            const int c00 = np * 16 + ocol;
            const float bx0 = __ldg(&bias[c00]),     by0 = __ldg(&bias[c00 + 1]);
            const float bx1 = __ldg(&bias[c00 + 8]), by1 = __ldg(&bias[c00 + 9]);
            if (orow0 < N) {
                float2* p = reinterpret_cast<float2*>(&out[orow0 * HIDDEN + c00]);
                p[0] = make_float2((acc0[0] + bx0) * scale, (acc0[1] + by0) * scale);
                p[4] = make_float2((acc1[0] + bx1) * scale, (acc1[1] + by1) * scale);
            }
            if (orow0 + 8 < N) {
                float2* p = reinterpret_cast<float2*>(&out[(orow0 + 8) * HIDDEN + c00]);
                p[0] = make_float2((acc0[2] + bx0) * scale, (acc0[3] + by0) * scale);
                p[4] = make_float2((acc1[2] + bx1) * scale, (acc1[3] + by1) * scale);
            }
        }
    }
}

// ---------------------------------------------------------------------------
// Attention: one warp per node, two passes (scores, then AV) to cut register
// pressure (~60 regs) and raise occupancy / memory-level parallelism.
// ---------------------------------------------------------------------------
__global__ __launch_bounds__(256) void k_attn(
    const int*           __restrict__ nbr_idx,
    const unsigned char* __restrict__ nbr_mask,
    float*               __restrict__ out, int N)
{
    const int warp = (blockIdx.x * blockDim.x + threadIdx.x) >> 5;
    const int lane = threadIdx.x & 31;
    if (warp >= N) return;
    const int n = warp;

    const int mask_i32 = g_mask_i32;

    int      jreg = 0;
    unsigned mreg = 0;
    if (lane < 16) {
        jreg = nbr_idx[n * 16 + lane];
        mreg = mask_i32
             ? (unsigned)reinterpret_cast<const int*>(nbr_mask)[n * 16 + lane]
             : (unsigned)nbr_mask[n * 16 + lane];
    }

    const float4 q4 = reinterpret_cast<const float4*>(g_q)[n * 32 + lane];

    // Pass 1: scores (k gather).
    float sc[16];
#pragma unroll
    for (int kk = 0; kk < 16; kk++) {
        const int      j = __shfl_sync(0xffffffffu, jreg, kk);
        const unsigned m = __shfl_sync(0xffffffffu, mreg, kk);
        const float4  kv = reinterpret_cast<const float4*>(g_k)[j * 32 + lane];
        float d = q4.x * kv.x + q4.y * kv.y + q4.z * kv.z + q4.w * kv.w;
        d += __shfl_xor_sync(0xffffffffu, d, 1);
        d += __shfl_xor_sync(0xffffffffu, d, 2);
        sc[kk] = m ? d : -1e9f;
    }

    // Softmax over 16 neighbors (per head; replicated in each 4-lane group).
    float mx = -1e30f;
#pragma unroll
    for (int kk = 0; kk < 16; kk++) mx = fmaxf(mx, sc[kk]);
    float s = 0.f;
#pragma unroll
    for (int kk = 0; kk < 16; kk++) { sc[kk] = __expf(sc[kk] - mx); s += sc[kk]; }
    const float inv = 1.f / s;

    // Pass 2: AV (v gather).
    float4 acc = make_float4(0.f, 0.f, 0.f, 0.f);
#pragma unroll
    for (int kk = 0; kk < 16; kk++) {
        const int    j = __shfl_sync(0xffffffffu, jreg, kk);
        const float  p = sc[kk] * inv;
        const float4 v = reinterpret_cast<const float4*>(g_v)[j * 32 + lane];
        acc.x = fmaf(p, v.x, acc.x);
        acc.y = fmaf(p, v.y, acc.y);
        acc.z = fmaf(p, v.z, acc.z);
        acc.w = fmaf(p, v.w, acc.w);
    }
    reinterpret_cast<float4*>(out)[n * 32 + lane] = acc;
}

// ---------------------------------------------------------------------------
// Launch
// ---------------------------------------------------------------------------
extern "C" void kernel_launch(void* const* d_in, const int* in_sizes, int n_in,
                              void* d_out, int out_size)
{
    const int*           X        = (const int*)d_in[0];
    const int*           nbr_idx  = (const int*)d_in[1];
    const unsigned char* nbr_mask = (const unsigned char*)d_in[2];
    const float*         emb      = (const float*)d_in[3];
    const float*         Wq       = (const float*)d_in[4];
    const float*         bq       = (const float*)d_in[5];
    const float*         Wk       = (const float*)d_in[6];
    const float*         bk       = (const float*)d_in[7];
    const float*         Wv       = (const float*)d_in[8];
    const float*         bv       = (const float*)d_in[9];
    float*               out      = (float*)d_out;

    const int N = in_sizes[0] / N_FEATS;

    k_prep<<<25, 512>>>(Wq, Wk, Wv, nbr_mask);

    const int smem_bytes = (TILE_M * HSTR) * 4 + TILE_M * N_FEATS * 4;  // ~72KB
    cudaFuncSetAttribute(k_encode_qkv,
                         cudaFuncAttributeMaxDynamicSharedMemorySize, smem_bytes);

    const int grid1 = (N + TILE_M - 1) / TILE_M;
    k_encode_qkv<<<grid1, 256, smem_bytes>>>(X, emb, bq, bk, bv, N);

    const int grid2 = (N + 7) / 8;
    k_attn<<<grid2, 256>>>(nbr_idx, nbr_mask, out, N);
}